// round 1
// baseline (speedup 1.0000x reference)
#include <cuda_runtime.h>
#include <math.h>

// Problem constants
#define BB   8
#define CC   256
#define KCC  32
#define NN   16384          // H*W = 128*128
#define TP   64             // pixels per tile
#define NBLK 64             // blocks per batch in pass 1
#define TPB  4              // tiles per block = (NN/TP)/NBLK = 256/64
#define XLD  68             // padded tile leading dim (bank-conflict avoidance)

// Scratch (device globals; no allocations allowed)
__device__ __align__(16) float g_qm[BB * KCC * NN];        // 16 MB: elu(q)+1
__device__ __align__(16) float g_Sp[BB * NBLK * KCC * CC]; // 16 MB: per-block partial S
__device__ __align__(16) float g_zp[BB * NBLK * KCC];      // partial z
__device__ __align__(16) float g_kv[BB * KCC * CC];        // kv context
__device__ __align__(16) float g_z [BB * KCC];             // z norm factor

extern __shared__ float sm1[];

// ---------------------------------------------------------------------------
// Pass 1: per 64-pixel tile:
//   qk[64,64] = Wqk[64,256] @ x[256,64]  (q rows 0..31, k rows 32..63)
//   qm = elu(q+bq)+1 -> g_qm ; km = elu(k+bk)+1 -> smem
//   S[32,256] += km @ x^T  (register-resident partial per block)
// ---------------------------------------------------------------------------
__global__ __launch_bounds__(256, 1)
void pass1_kernel(const float* __restrict__ x,
                  const float* __restrict__ Wq, const float* __restrict__ bq,
                  const float* __restrict__ Wk, const float* __restrict__ bk)
{
    float* Ws  = sm1;                 // [c][r]  256 x 64 (transposed combined Wq|Wk)
    float* xs  = Ws + 256 * 64;       // [c][p]  256 x XLD
    float* kms = xs + 256 * XLD;      // [kc][p] 32 x XLD

    const int tid = threadIdx.x;
    const int b   = blockIdx.y;
    const int blk = blockIdx.x;
    const int ty  = tid >> 4;         // 0..15
    const int tx  = tid & 15;         // 0..15

    // Load combined weights transposed: Ws[c][r]
    for (int i = tid; i < 64 * 256; i += 256) {
        int r = i & 63, c = i >> 6;
        Ws[c * 64 + r] = (r < KCC) ? Wq[r * CC + c] : Wk[(r - KCC) * CC + c];
    }

    float bias[4];
#pragma unroll
    for (int i = 0; i < 4; i++) {
        int r = ty * 4 + i;
        bias[i] = (r < KCC) ? bq[r] : bk[r - KCC];
    }

    // Persistent S accumulators: thread owns kc = tid>>3, c = (tid&7) + 8*j
    float Sacc[32];
#pragma unroll
    for (int j = 0; j < 32; j++) Sacc[j] = 0.f;
    float zacc = 0.f;
    const int kcS = tid >> 3;
    const int c0S = tid & 7;

    __syncthreads();

    for (int t = 0; t < TPB; t++) {
        const int n0 = (blk * TPB + t) * TP;
        const float* xb = x + (b * CC) * NN + n0;

        // ---- Stage A: load x tile [256][64] ----
        for (int i = tid; i < 256 * 16; i += 256) {
            int fx = i & 15, c = i >> 4;
            float4 v = *(const float4*)(xb + c * NN + fx * 4);
            *(float4*)&xs[c * XLD + fx * 4] = v;
        }
        __syncthreads();

        // ---- Stage B: 64x64x256 GEMM (register-tiled 4x4) ----
        float acc[4][4];
#pragma unroll
        for (int i = 0; i < 4; i++)
#pragma unroll
            for (int j = 0; j < 4; j++) acc[i][j] = 0.f;

#pragma unroll 4
        for (int k = 0; k < 256; k++) {
            float4 a = *(float4*)&Ws[k * 64 + ty * 4];
            float4 p = *(float4*)&xs[k * XLD + tx * 4];
            acc[0][0] = fmaf(a.x, p.x, acc[0][0]);
            acc[0][1] = fmaf(a.x, p.y, acc[0][1]);
            acc[0][2] = fmaf(a.x, p.z, acc[0][2]);
            acc[0][3] = fmaf(a.x, p.w, acc[0][3]);
            acc[1][0] = fmaf(a.y, p.x, acc[1][0]);
            acc[1][1] = fmaf(a.y, p.y, acc[1][1]);
            acc[1][2] = fmaf(a.y, p.z, acc[1][2]);
            acc[1][3] = fmaf(a.y, p.w, acc[1][3]);
            acc[2][0] = fmaf(a.z, p.x, acc[2][0]);
            acc[2][1] = fmaf(a.z, p.y, acc[2][1]);
            acc[2][2] = fmaf(a.z, p.z, acc[2][2]);
            acc[2][3] = fmaf(a.z, p.w, acc[2][3]);
            acc[3][0] = fmaf(a.w, p.x, acc[3][0]);
            acc[3][1] = fmaf(a.w, p.y, acc[3][1]);
            acc[3][2] = fmaf(a.w, p.z, acc[3][2]);
            acc[3][3] = fmaf(a.w, p.w, acc[3][3]);
        }

        // bias + elu + 1  (elu(x)+1 = x+1 if x>0 else exp(x))
#pragma unroll
        for (int i = 0; i < 4; i++)
#pragma unroll
            for (int j = 0; j < 4; j++) {
                float v = acc[i][j] + bias[i];
                acc[i][j] = (v > 0.f) ? (v + 1.f) : __expf(v);
            }

        if (ty < 8) {
            // q rows -> global qm
#pragma unroll
            for (int i = 0; i < 4; i++) {
                int r = ty * 4 + i;
                *(float4*)&g_qm[(b * KCC + r) * NN + n0 + tx * 4] =
                    make_float4(acc[i][0], acc[i][1], acc[i][2], acc[i][3]);
            }
        } else {
            // k rows -> smem for S accumulation
#pragma unroll
            for (int i = 0; i < 4; i++) {
                int kc = ty * 4 + i - KCC;
                *(float4*)&kms[kc * XLD + tx * 4] =
                    make_float4(acc[i][0], acc[i][1], acc[i][2], acc[i][3]);
            }
        }
        __syncthreads();

        // ---- Stage C: S[kc][c] += sum_p km[kc][p] * x[c][p] ----
#pragma unroll 2
        for (int p4 = 0; p4 < 16; p4++) {
            float4 km4 = *(float4*)&kms[kcS * XLD + p4 * 4];
            if (c0S == 0) zacc += (km4.x + km4.y) + (km4.z + km4.w);
#pragma unroll
            for (int j = 0; j < 32; j++) {
                float4 xv = *(float4*)&xs[(c0S + 8 * j) * XLD + p4 * 4];
                float s = Sacc[j];
                s = fmaf(km4.x, xv.x, s);
                s = fmaf(km4.y, xv.y, s);
                s = fmaf(km4.z, xv.z, s);
                s = fmaf(km4.w, xv.w, s);
                Sacc[j] = s;
            }
        }
        __syncthreads();
    }

    // Write per-block partials
    float* Sp = g_Sp + ((b * NBLK + blk) * KCC + kcS) * CC;
#pragma unroll
    for (int j = 0; j < 32; j++) Sp[c0S + 8 * j] = Sacc[j];
    if (c0S == 0) g_zp[(b * NBLK + blk) * KCC + kcS] = zacc;
}

// ---------------------------------------------------------------------------
// Reduce partials, then kv = S @ Wv^T + z * bv^T  (tiny: 2M MAC / batch)
// ---------------------------------------------------------------------------
__global__ __launch_bounds__(256)
void reduce_kv_kernel(const float* __restrict__ Wv, const float* __restrict__ bv)
{
    __shared__ float Ssm[KCC * CC];
    __shared__ float zsm[KCC];
    const int tid = threadIdx.x;
    const int b = blockIdx.x;

    for (int i = tid; i < KCC * CC; i += 256) {
        float s = 0.f;
        for (int r = 0; r < NBLK; r++) s += g_Sp[(b * NBLK + r) * KCC * CC + i];
        Ssm[i] = s;
    }
    if (tid < KCC) {
        float z = 0.f;
        for (int r = 0; r < NBLK; r++) z += g_zp[(b * NBLK + r) * KCC + tid];
        zsm[tid] = z;
        g_z[b * KCC + tid] = z;
    }
    __syncthreads();

    const int kc = tid >> 3, v0 = tid & 7;
    for (int j = 0; j < 32; j++) {
        int vc = v0 + 8 * j;
        float acc = zsm[kc] * bv[vc];
        const float* wr = Wv + vc * CC;
        const float* sr = Ssm + kc * CC;
#pragma unroll 8
        for (int c4 = 0; c4 < 64; c4++) {
            float4 w = *(const float4*)&wr[c4 * 4];
            float4 s = *(const float4*)&sr[c4 * 4];
            acc = fmaf(w.x, s.x, acc);
            acc = fmaf(w.y, s.y, acc);
            acc = fmaf(w.z, s.z, acc);
            acc = fmaf(w.w, s.w, acc);
        }
        g_kv[(b * KCC + kc) * CC + vc] = acc;
    }
}

// ---------------------------------------------------------------------------
// Pass 2: out[c,n] = gamma * (sum_k qm[k,n]*kv[k,c]) / max(qm[.,n]·z, 1e-6) + x[c,n]
// ---------------------------------------------------------------------------
__global__ __launch_bounds__(256, 2)
void pass2_kernel(const float* __restrict__ x,
                  const float* __restrict__ gamma,
                  float* __restrict__ out)
{
    __shared__ float kvT[KCC * CC];    // [k][vc]
    __shared__ float qms[KCC * XLD];   // [k][p]
    __shared__ float zsm[KCC];

    const int tid = threadIdx.x;
    const int b   = blockIdx.y;
    const int n0  = blockIdx.x * TP;
    const int ty  = tid >> 4;
    const int tx  = tid & 15;

    for (int i = tid; i < KCC * CC; i += 256) kvT[i] = g_kv[b * KCC * CC + i];
    if (tid < KCC) zsm[tid] = g_z[b * KCC + tid];
    for (int i = tid; i < KCC * 16; i += 256) {
        int k = i >> 4, fx = i & 15;
        *(float4*)&qms[k * XLD + fx * 4] =
            *(const float4*)&g_qm[(b * KCC + k) * NN + n0 + fx * 4];
    }
    __syncthreads();

    float acc[16][4];
#pragma unroll
    for (int i = 0; i < 16; i++)
#pragma unroll
        for (int j = 0; j < 4; j++) acc[i][j] = 0.f;
    float qz[4] = {0.f, 0.f, 0.f, 0.f};

#pragma unroll 2
    for (int k = 0; k < KCC; k++) {
        float4 p = *(float4*)&qms[k * XLD + tx * 4];
        float zk = zsm[k];
        qz[0] = fmaf(zk, p.x, qz[0]);
        qz[1] = fmaf(zk, p.y, qz[1]);
        qz[2] = fmaf(zk, p.z, qz[2]);
        qz[3] = fmaf(zk, p.w, qz[3]);
#pragma unroll
        for (int i4 = 0; i4 < 4; i4++) {
            float4 a = *(float4*)&kvT[k * CC + ty * 16 + i4 * 4];
            float av[4] = {a.x, a.y, a.z, a.w};
#pragma unroll
            for (int m = 0; m < 4; m++) {
                int i = i4 * 4 + m;
                acc[i][0] = fmaf(av[m], p.x, acc[i][0]);
                acc[i][1] = fmaf(av[m], p.y, acc[i][1]);
                acc[i][2] = fmaf(av[m], p.z, acc[i][2]);
                acc[i][3] = fmaf(av[m], p.w, acc[i][3]);
            }
        }
    }

    const float gam = gamma[0];
    float inv[4];
#pragma unroll
    for (int j = 0; j < 4; j++) inv[j] = gam / fmaxf(qz[j], 1e-6f);

#pragma unroll
    for (int i = 0; i < 16; i++) {
        int c = ty * 16 + i;
        int gidx = (b * CC + c) * NN + n0 + tx * 4;
        float4 xv = *(const float4*)&x[gidx];
        float4 o;
        o.x = fmaf(acc[i][0], inv[0], xv.x);
        o.y = fmaf(acc[i][1], inv[1], xv.y);
        o.z = fmaf(acc[i][2], inv[2], xv.z);
        o.w = fmaf(acc[i][3], inv[3], xv.w);
        *(float4*)&out[gidx] = o;
    }
}

// ---------------------------------------------------------------------------
extern "C" void kernel_launch(void* const* d_in, const int* in_sizes, int n_in,
                              void* d_out, int out_size)
{
    const float* x     = (const float*)d_in[0];
    const float* Wq    = (const float*)d_in[1];
    const float* bq    = (const float*)d_in[2];
    const float* Wk    = (const float*)d_in[3];
    const float* bk    = (const float*)d_in[4];
    const float* Wv    = (const float*)d_in[5];
    const float* bv    = (const float*)d_in[6];
    const float* gamma = (const float*)d_in[7];
    float* out = (float*)d_out;

    size_t smem1 = (256 * 64 + 256 * XLD + KCC * XLD) * sizeof(float); // ~140 KB
    cudaFuncSetAttribute(pass1_kernel, cudaFuncAttributeMaxDynamicSharedMemorySize,
                         (int)smem1);

    pass1_kernel<<<dim3(NBLK, BB), 256, smem1>>>(x, Wq, bq, Wk, bk);
    reduce_kv_kernel<<<BB, 256>>>(Wv, bv);
    pass2_kernel<<<dim3(NN / TP, BB), 256>>>(x, gamma, out);
}

// round 2
// speedup vs baseline: 2.8424x; 2.8424x over previous
#include <cuda_runtime.h>
#include <math.h>

#define BB   8
#define CC   256
#define KCC  32
#define NN   16384
#define TP   64
#define NBLK 64
#define TPB  4
#define XLD  68

// Scratch (device globals; no allocations allowed)
__device__ __align__(16) float g_qm[BB * KCC * NN];   // 16 MB
__device__ __align__(16) float g_S [BB * KCC * CC];   // 256 KB, atomically accumulated
__device__ __align__(16) float g_z [BB * KCC];
__device__ __align__(16) float g_kv[BB * KCC * CC];
__device__ __align__(16) float g_zf[BB * KCC];

extern __shared__ float sm1[];

__device__ __forceinline__ void cp_async16(void* smem_dst, const void* gmem_src) {
    unsigned sa = (unsigned)__cvta_generic_to_shared(smem_dst);
    asm volatile("cp.async.cg.shared.global [%0], [%1], 16;\n" :: "r"(sa), "l"(gmem_src));
}

// ---------------------------------------------------------------------------
// Zero the atomic accumulators
// ---------------------------------------------------------------------------
__global__ void zero_kernel() {
    int i = blockIdx.x * 256 + threadIdx.x;
    if (i < BB * KCC * CC) g_S[i] = 0.f;
    if (i < BB * KCC) g_z[i] = 0.f;
}

// ---------------------------------------------------------------------------
// Pass 1: projection GEMM + elu+1 + S/z accumulation (double-buffered cp.async)
// ---------------------------------------------------------------------------
__global__ __launch_bounds__(256, 1)
void pass1_kernel(const float* __restrict__ x,
                  const float* __restrict__ Wq, const float* __restrict__ bq,
                  const float* __restrict__ Wk, const float* __restrict__ bk)
{
    float* Ws  = sm1;                      // [c][r]  256 x 64
    float* xs0 = Ws + 256 * 64;            // [c][p]  256 x XLD  (buffer 0)
    float* xs1 = xs0 + 256 * XLD;          //                    (buffer 1)
    float* kms = xs1 + 256 * XLD;          // [kc][p] 32 x XLD

    const int tid = threadIdx.x;
    const int b   = blockIdx.y;
    const int blk = blockIdx.x;
    const int ty  = tid >> 4;
    const int tx  = tid & 15;

    for (int i = tid; i < 64 * 256; i += 256) {
        int r = i & 63, c = i >> 6;
        Ws[c * 64 + r] = (r < KCC) ? Wq[r * CC + c] : Wk[(r - KCC) * CC + c];
    }

    float bias[4];
#pragma unroll
    for (int i = 0; i < 4; i++) {
        int r = ty * 4 + i;
        bias[i] = (r < KCC) ? bq[r] : bk[r - KCC];
    }

    float Sacc[32];
#pragma unroll
    for (int j = 0; j < 32; j++) Sacc[j] = 0.f;
    float zacc = 0.f;
    const int kcS = tid >> 3;
    const int c0S = tid & 7;

    const float* xbase = x + (size_t)(b * CC) * NN;

    // Prefetch tile 0 into buffer 0
    {
        const float* xb = xbase + (blk * TPB) * TP;
        for (int i = tid; i < 256 * 16; i += 256) {
            int fx = i & 15, c = i >> 4;
            cp_async16(&xs0[c * XLD + fx * 4], xb + c * NN + fx * 4);
        }
        asm volatile("cp.async.commit_group;\n");
    }

    for (int t = 0; t < TPB; t++) {
        float* xs = (t & 1) ? xs1 : xs0;

        // Issue next tile into the other buffer, then wait for current
        if (t + 1 < TPB) {
            float* xsn = ((t + 1) & 1) ? xs1 : xs0;
            const float* xb = xbase + (blk * TPB + t + 1) * TP;
            for (int i = tid; i < 256 * 16; i += 256) {
                int fx = i & 15, c = i >> 4;
                cp_async16(&xsn[c * XLD + fx * 4], xb + c * NN + fx * 4);
            }
            asm volatile("cp.async.commit_group;\n");
            asm volatile("cp.async.wait_group 1;\n");
        } else {
            asm volatile("cp.async.wait_group 0;\n");
        }
        __syncthreads();

        // ---- Stage B: 64x64x256 GEMM (register-tiled 4x4) ----
        float acc[4][4];
#pragma unroll
        for (int i = 0; i < 4; i++)
#pragma unroll
            for (int j = 0; j < 4; j++) acc[i][j] = 0.f;

#pragma unroll 8
        for (int k = 0; k < 256; k++) {
            float4 a = *(float4*)&Ws[k * 64 + ty * 4];
            float4 p = *(float4*)&xs[k * XLD + tx * 4];
            acc[0][0] = fmaf(a.x, p.x, acc[0][0]);
            acc[0][1] = fmaf(a.x, p.y, acc[0][1]);
            acc[0][2] = fmaf(a.x, p.z, acc[0][2]);
            acc[0][3] = fmaf(a.x, p.w, acc[0][3]);
            acc[1][0] = fmaf(a.y, p.x, acc[1][0]);
            acc[1][1] = fmaf(a.y, p.y, acc[1][1]);
            acc[1][2] = fmaf(a.y, p.z, acc[1][2]);
            acc[1][3] = fmaf(a.y, p.w, acc[1][3]);
            acc[2][0] = fmaf(a.z, p.x, acc[2][0]);
            acc[2][1] = fmaf(a.z, p.y, acc[2][1]);
            acc[2][2] = fmaf(a.z, p.z, acc[2][2]);
            acc[2][3] = fmaf(a.z, p.w, acc[2][3]);
            acc[3][0] = fmaf(a.w, p.x, acc[3][0]);
            acc[3][1] = fmaf(a.w, p.y, acc[3][1]);
            acc[3][2] = fmaf(a.w, p.z, acc[3][2]);
            acc[3][3] = fmaf(a.w, p.w, acc[3][3]);
        }

        const int n0 = (blk * TPB + t) * TP;
#pragma unroll
        for (int i = 0; i < 4; i++)
#pragma unroll
            for (int j = 0; j < 4; j++) {
                float v = acc[i][j] + bias[i];
                acc[i][j] = (v > 0.f) ? (v + 1.f) : __expf(v);
            }

        if (ty < 8) {
#pragma unroll
            for (int i = 0; i < 4; i++) {
                int r = ty * 4 + i;
                *(float4*)&g_qm[(size_t)(b * KCC + r) * NN + n0 + tx * 4] =
                    make_float4(acc[i][0], acc[i][1], acc[i][2], acc[i][3]);
            }
        } else {
#pragma unroll
            for (int i = 0; i < 4; i++) {
                int kc = ty * 4 + i - KCC;
                *(float4*)&kms[kc * XLD + tx * 4] =
                    make_float4(acc[i][0], acc[i][1], acc[i][2], acc[i][3]);
            }
        }
        __syncthreads();

        // ---- Stage C: S[kc][c] += sum_p km[kc][p] * x[c][p] ----
#pragma unroll 2
        for (int p4 = 0; p4 < 16; p4++) {
            float4 km4 = *(float4*)&kms[kcS * XLD + p4 * 4];
            if (c0S == 0) zacc += (km4.x + km4.y) + (km4.z + km4.w);
#pragma unroll
            for (int j = 0; j < 32; j++) {
                float4 xv = *(float4*)&xs[(c0S + 8 * j) * XLD + p4 * 4];
                float s = Sacc[j];
                s = fmaf(km4.x, xv.x, s);
                s = fmaf(km4.y, xv.y, s);
                s = fmaf(km4.z, xv.z, s);
                s = fmaf(km4.w, xv.w, s);
                Sacc[j] = s;
            }
        }
        __syncthreads();
    }

    // Atomic accumulation into the small global S/z
    float* Sg = g_S + (b * KCC + kcS) * CC;
#pragma unroll
    for (int j = 0; j < 32; j++) atomicAdd(&Sg[c0S + 8 * j], Sacc[j]);
    if (c0S == 0) atomicAdd(&g_z[b * KCC + kcS], zacc);
}

// ---------------------------------------------------------------------------
// kv = S @ Wv^T + z * bv^T    grid (8 vslices, 8 batches)
// ---------------------------------------------------------------------------
__global__ __launch_bounds__(256)
void kv_kernel(const float* __restrict__ Wv, const float* __restrict__ bv)
{
    __shared__ float Ssm[KCC * CC];     // 32 KB
    __shared__ float Wsm[32 * CC];      // 32 KB  (this block's 32 v-rows)
    __shared__ float zsm[KCC];

    const int tid = threadIdx.x;
    const int b   = blockIdx.y;
    const int v0  = blockIdx.x * 32;

    for (int i = tid; i < KCC * CC / 4; i += 256)
        *(float4*)&Ssm[i * 4] = *(const float4*)&g_S[b * KCC * CC + i * 4];
    for (int i = tid; i < 32 * CC / 4; i += 256)
        *(float4*)&Wsm[i * 4] = *(const float4*)&Wv[v0 * CC + i * 4];
    if (tid < KCC) {
        float z = g_z[b * KCC + tid];
        zsm[tid] = z;
        if (blockIdx.x == 0) g_zf[b * KCC + tid] = z;
    }
    __syncthreads();

    const int kc = tid >> 3, j0 = tid & 7;
#pragma unroll
    for (int j = 0; j < 4; j++) {
        int vl = j0 + 8 * j;                 // 0..31 local v row
        float acc = zsm[kc] * bv[v0 + vl];
        const float* wr = Wsm + vl * CC;
        const float* sr = Ssm + kc * CC;
#pragma unroll 8
        for (int c4 = 0; c4 < 64; c4++) {
            float4 w = *(const float4*)&wr[c4 * 4];
            float4 s = *(const float4*)&sr[c4 * 4];
            acc = fmaf(w.x, s.x, acc);
            acc = fmaf(w.y, s.y, acc);
            acc = fmaf(w.z, s.z, acc);
            acc = fmaf(w.w, s.w, acc);
        }
        g_kv[(b * KCC + kc) * CC + v0 + vl] = acc;
    }
}

// ---------------------------------------------------------------------------
// Pass 2: out = gamma * (kv^T @ qm) / max(qm . z, 1e-6) + x
// grid (NN/64, 2 ch-halves, 8 batches), 256 thr, thread tile 8ch x 4px
// ---------------------------------------------------------------------------
__global__ __launch_bounds__(256)
void pass2_kernel(const float* __restrict__ x,
                  const float* __restrict__ gamma,
                  float* __restrict__ out)
{
    __shared__ float kvh[KCC * 128];     // 16 KB: kv[k][ch-half]
    __shared__ float qms[KCC * XLD];     // 8.7 KB
    __shared__ float zsm[KCC];

    const int tid  = threadIdx.x;
    const int b    = blockIdx.z;
    const int half = blockIdx.y;
    const int n0   = blockIdx.x * TP;
    const int ty   = tid >> 4;           // 0..15 (8-channel group)
    const int tx   = tid & 15;           // 0..15 (4-pixel group)

    for (int i = tid; i < KCC * 32; i += 256) {
        int k = i >> 5, c4 = i & 31;
        *(float4*)&kvh[k * 128 + c4 * 4] =
            *(const float4*)&g_kv[(b * KCC + k) * CC + half * 128 + c4 * 4];
    }
    for (int i = tid; i < KCC * 16; i += 256) {
        int k = i >> 4, fx = i & 15;
        *(float4*)&qms[k * XLD + fx * 4] =
            *(const float4*)&g_qm[(size_t)(b * KCC + k) * NN + n0 + fx * 4];
    }
    if (tid < KCC) zsm[tid] = g_zf[b * KCC + tid];
    __syncthreads();

    float acc[8][4];
#pragma unroll
    for (int i = 0; i < 8; i++)
#pragma unroll
        for (int j = 0; j < 4; j++) acc[i][j] = 0.f;
    float qz[4] = {0.f, 0.f, 0.f, 0.f};

#pragma unroll 4
    for (int k = 0; k < KCC; k++) {
        float4 p = *(float4*)&qms[k * XLD + tx * 4];
        float zk = zsm[k];
        qz[0] = fmaf(zk, p.x, qz[0]);
        qz[1] = fmaf(zk, p.y, qz[1]);
        qz[2] = fmaf(zk, p.z, qz[2]);
        qz[3] = fmaf(zk, p.w, qz[3]);
        float4 a0 = *(float4*)&kvh[k * 128 + ty * 8];
        float4 a1 = *(float4*)&kvh[k * 128 + ty * 8 + 4];
        float av[8] = {a0.x, a0.y, a0.z, a0.w, a1.x, a1.y, a1.z, a1.w};
#pragma unroll
        for (int i = 0; i < 8; i++) {
            acc[i][0] = fmaf(av[i], p.x, acc[i][0]);
            acc[i][1] = fmaf(av[i], p.y, acc[i][1]);
            acc[i][2] = fmaf(av[i], p.z, acc[i][2]);
            acc[i][3] = fmaf(av[i], p.w, acc[i][3]);
        }
    }

    const float gam = gamma[0];
    float inv[4];
#pragma unroll
    for (int j = 0; j < 4; j++) inv[j] = gam / fmaxf(qz[j], 1e-6f);

#pragma unroll
    for (int i = 0; i < 8; i++) {
        int c = half * 128 + ty * 8 + i;
        size_t gidx = (size_t)(b * CC + c) * NN + n0 + tx * 4;
        float4 xv = *(const float4*)&x[gidx];
        float4 o;
        o.x = fmaf(acc[i][0], inv[0], xv.x);
        o.y = fmaf(acc[i][1], inv[1], xv.y);
        o.z = fmaf(acc[i][2], inv[2], xv.z);
        o.w = fmaf(acc[i][3], inv[3], xv.w);
        *(float4*)&out[gidx] = o;
    }
}

// ---------------------------------------------------------------------------
extern "C" void kernel_launch(void* const* d_in, const int* in_sizes, int n_in,
                              void* d_out, int out_size)
{
    const float* x     = (const float*)d_in[0];
    const float* Wq    = (const float*)d_in[1];
    const float* bq    = (const float*)d_in[2];
    const float* Wk    = (const float*)d_in[3];
    const float* bk    = (const float*)d_in[4];
    const float* Wv    = (const float*)d_in[5];
    const float* bv    = (const float*)d_in[6];
    const float* gamma = (const float*)d_in[7];
    float* out = (float*)d_out;

    size_t smem1 = (256 * 64 + 2 * 256 * XLD + KCC * XLD) * sizeof(float); // ~213 KB
    static int inited = 0;
    cudaFuncSetAttribute(pass1_kernel, cudaFuncAttributeMaxDynamicSharedMemorySize,
                         (int)smem1);
    (void)inited;

    zero_kernel<<<(BB * KCC * CC + 255) / 256, 256>>>();
    pass1_kernel<<<dim3(NBLK, BB), 256, smem1>>>(x, Wq, bq, Wk, bk);
    kv_kernel<<<dim3(8, BB), 256>>>(Wv, bv);
    pass2_kernel<<<dim3(NN / TP, 2, BB), 256>>>(x, gamma, out);
}

// round 3
// speedup vs baseline: 2.8527x; 1.0036x over previous
#include <cuda_runtime.h>
#include <math.h>

#define BB   8
#define CC   256
#define KCC  32
#define NN   16384
#define TP   64
#define NBLK 64
#define TPB  4
#define XLD  68

// Scratch (device globals; no allocations allowed)
__device__ __align__(16) float g_qm[BB * KCC * NN];   // 16 MB
__device__ __align__(16) float g_S [BB * KCC * CC];   // 256 KB, atomically accumulated
__device__ __align__(16) float g_z [BB * KCC];
__device__ __align__(16) float g_kv[BB * KCC * CC];
__device__ __align__(16) float g_zf[BB * KCC];

extern __shared__ float sm1[];

__device__ __forceinline__ void cp_async16(void* smem_dst, const void* gmem_src) {
    unsigned sa = (unsigned)__cvta_generic_to_shared(smem_dst);
    asm volatile("cp.async.cg.shared.global [%0], [%1], 16;\n" :: "r"(sa), "l"(gmem_src));
}

// ---------------------------------------------------------------------------
// Zero the atomic accumulators
// ---------------------------------------------------------------------------
__global__ void zero_kernel() {
    int i = blockIdx.x * 256 + threadIdx.x;
    if (i < BB * KCC * CC) g_S[i] = 0.f;
    if (i < BB * KCC) g_z[i] = 0.f;
}

// ---------------------------------------------------------------------------
// Pass 1: projection GEMM + elu+1 + S/z accumulation (double-buffered cp.async)
// ---------------------------------------------------------------------------
__global__ __launch_bounds__(256, 1)
void pass1_kernel(const float* __restrict__ x,
                  const float* __restrict__ Wq, const float* __restrict__ bq,
                  const float* __restrict__ Wk, const float* __restrict__ bk)
{
    float* Ws  = sm1;                      // [c][r]  256 x 64
    float* xs0 = Ws + 256 * 64;            // [c][p]  256 x XLD  (buffer 0)
    float* xs1 = xs0 + 256 * XLD;          //                    (buffer 1)
    float* kms = xs1 + 256 * XLD;          // [kc][p] 32 x XLD

    const int tid = threadIdx.x;
    const int b   = blockIdx.y;
    const int blk = blockIdx.x;
    const int ty  = tid >> 4;
    const int tx  = tid & 15;

    for (int i = tid; i < 64 * 256; i += 256) {
        int r = i & 63, c = i >> 6;
        Ws[c * 64 + r] = (r < KCC) ? Wq[r * CC + c] : Wk[(r - KCC) * CC + c];
    }

    float bias[4];
#pragma unroll
    for (int i = 0; i < 4; i++) {
        int r = ty * 4 + i;
        bias[i] = (r < KCC) ? bq[r] : bk[r - KCC];
    }

    float Sacc[32];
#pragma unroll
    for (int j = 0; j < 32; j++) Sacc[j] = 0.f;
    float zacc = 0.f;
    const int kcS = tid >> 3;
    const int c0S = tid & 7;

    const float* xbase = x + (size_t)(b * CC) * NN;

    // Prefetch tile 0 into buffer 0
    {
        const float* xb = xbase + (blk * TPB) * TP;
        for (int i = tid; i < 256 * 16; i += 256) {
            int fx = i & 15, c = i >> 4;
            cp_async16(&xs0[c * XLD + fx * 4], xb + c * NN + fx * 4);
        }
        asm volatile("cp.async.commit_group;\n");
    }

    for (int t = 0; t < TPB; t++) {
        float* xs = (t & 1) ? xs1 : xs0;

        // Issue next tile into the other buffer, then wait for current
        if (t + 1 < TPB) {
            float* xsn = ((t + 1) & 1) ? xs1 : xs0;
            const float* xb = xbase + (blk * TPB + t + 1) * TP;
            for (int i = tid; i < 256 * 16; i += 256) {
                int fx = i & 15, c = i >> 4;
                cp_async16(&xsn[c * XLD + fx * 4], xb + c * NN + fx * 4);
            }
            asm volatile("cp.async.commit_group;\n");
            asm volatile("cp.async.wait_group 1;\n");
        } else {
            asm volatile("cp.async.wait_group 0;\n");
        }
        __syncthreads();

        // ---- Stage B: 64x64x256 GEMM (register-tiled 4x4) ----
        float acc[4][4];
#pragma unroll
        for (int i = 0; i < 4; i++)
#pragma unroll
            for (int j = 0; j < 4; j++) acc[i][j] = 0.f;

#pragma unroll 8
        for (int k = 0; k < 256; k++) {
            float4 a = *(float4*)&Ws[k * 64 + ty * 4];
            float4 p = *(float4*)&xs[k * XLD + tx * 4];
            acc[0][0] = fmaf(a.x, p.x, acc[0][0]);
            acc[0][1] = fmaf(a.x, p.y, acc[0][1]);
            acc[0][2] = fmaf(a.x, p.z, acc[0][2]);
            acc[0][3] = fmaf(a.x, p.w, acc[0][3]);
            acc[1][0] = fmaf(a.y, p.x, acc[1][0]);
            acc[1][1] = fmaf(a.y, p.y, acc[1][1]);
            acc[1][2] = fmaf(a.y, p.z, acc[1][2]);
            acc[1][3] = fmaf(a.y, p.w, acc[1][3]);
            acc[2][0] = fmaf(a.z, p.x, acc[2][0]);
            acc[2][1] = fmaf(a.z, p.y, acc[2][1]);
            acc[2][2] = fmaf(a.z, p.z, acc[2][2]);
            acc[2][3] = fmaf(a.z, p.w, acc[2][3]);
            acc[3][0] = fmaf(a.w, p.x, acc[3][0]);
            acc[3][1] = fmaf(a.w, p.y, acc[3][1]);
            acc[3][2] = fmaf(a.w, p.z, acc[3][2]);
            acc[3][3] = fmaf(a.w, p.w, acc[3][3]);
        }

        const int n0 = (blk * TPB + t) * TP;
#pragma unroll
        for (int i = 0; i < 4; i++)
#pragma unroll
            for (int j = 0; j < 4; j++) {
                float v = acc[i][j] + bias[i];
                acc[i][j] = (v > 0.f) ? (v + 1.f) : __expf(v);
            }

        if (ty < 8) {
#pragma unroll
            for (int i = 0; i < 4; i++) {
                int r = ty * 4 + i;
                *(float4*)&g_qm[(size_t)(b * KCC + r) * NN + n0 + tx * 4] =
                    make_float4(acc[i][0], acc[i][1], acc[i][2], acc[i][3]);
            }
        } else {
#pragma unroll
            for (int i = 0; i < 4; i++) {
                int kc = ty * 4 + i - KCC;
                *(float4*)&kms[kc * XLD + tx * 4] =
                    make_float4(acc[i][0], acc[i][1], acc[i][2], acc[i][3]);
            }
        }
        __syncthreads();

        // ---- Stage C: S[kc][c] += sum_p km[kc][p] * x[c][p] ----
#pragma unroll 2
        for (int p4 = 0; p4 < 16; p4++) {
            float4 km4 = *(float4*)&kms[kcS * XLD + p4 * 4];
            if (c0S == 0) zacc += (km4.x + km4.y) + (km4.z + km4.w);
#pragma unroll
            for (int j = 0; j < 32; j++) {
                float4 xv = *(float4*)&xs[(c0S + 8 * j) * XLD + p4 * 4];
                float s = Sacc[j];
                s = fmaf(km4.x, xv.x, s);
                s = fmaf(km4.y, xv.y, s);
                s = fmaf(km4.z, xv.z, s);
                s = fmaf(km4.w, xv.w, s);
                Sacc[j] = s;
            }
        }
        __syncthreads();
    }

    // Atomic accumulation into the small global S/z
    float* Sg = g_S + (b * KCC + kcS) * CC;
#pragma unroll
    for (int j = 0; j < 32; j++) atomicAdd(&Sg[c0S + 8 * j], Sacc[j]);
    if (c0S == 0) atomicAdd(&g_z[b * KCC + kcS], zacc);
}

// ---------------------------------------------------------------------------
// kv = S @ Wv^T + z * bv^T    grid (8 vslices, 8 batches)
// ---------------------------------------------------------------------------
__global__ __launch_bounds__(256)
void kv_kernel(const float* __restrict__ Wv, const float* __restrict__ bv)
{
    __shared__ float Ssm[KCC * CC];     // 32 KB
    __shared__ float Wsm[32 * CC];      // 32 KB  (this block's 32 v-rows)
    __shared__ float zsm[KCC];

    const int tid = threadIdx.x;
    const int b   = blockIdx.y;
    const int v0  = blockIdx.x * 32;

    for (int i = tid; i < KCC * CC / 4; i += 256)
        *(float4*)&Ssm[i * 4] = *(const float4*)&g_S[b * KCC * CC + i * 4];
    for (int i = tid; i < 32 * CC / 4; i += 256)
        *(float4*)&Wsm[i * 4] = *(const float4*)&Wv[v0 * CC + i * 4];
    if (tid < KCC) {
        float z = g_z[b * KCC + tid];
        zsm[tid] = z;
        if (blockIdx.x == 0) g_zf[b * KCC + tid] = z;
    }
    __syncthreads();

    const int kc = tid >> 3, j0 = tid & 7;
#pragma unroll
    for (int j = 0; j < 4; j++) {
        int vl = j0 + 8 * j;                 // 0..31 local v row
        float acc = zsm[kc] * bv[v0 + vl];
        const float* wr = Wsm + vl * CC;
        const float* sr = Ssm + kc * CC;
#pragma unroll 8
        for (int c4 = 0; c4 < 64; c4++) {
            float4 w = *(const float4*)&wr[c4 * 4];
            float4 s = *(const float4*)&sr[c4 * 4];
            acc = fmaf(w.x, s.x, acc);
            acc = fmaf(w.y, s.y, acc);
            acc = fmaf(w.z, s.z, acc);
            acc = fmaf(w.w, s.w, acc);
        }
        g_kv[(b * KCC + kc) * CC + v0 + vl] = acc;
    }
}

// ---------------------------------------------------------------------------
// Pass 2: out = gamma * (kv^T @ qm) / max(qm . z, 1e-6) + x
// grid (NN/64, 2 ch-halves, 8 batches), 256 thr, thread tile 8ch x 4px
// ---------------------------------------------------------------------------
__global__ __launch_bounds__(256)
void pass2_kernel(const float* __restrict__ x,
                  const float* __restrict__ gamma,
                  float* __restrict__ out)
{
    __shared__ float kvh[KCC * 128];     // 16 KB: kv[k][ch-half]
    __shared__ float qms[KCC * XLD];     // 8.7 KB
    __shared__ float zsm[KCC];

    const int tid  = threadIdx.x;
    const int b    = blockIdx.z;
    const int half = blockIdx.y;
    const int n0   = blockIdx.x * TP;
    const int ty   = tid >> 4;           // 0..15 (8-channel group)
    const int tx   = tid & 15;           // 0..15 (4-pixel group)

    for (int i = tid; i < KCC * 32; i += 256) {
        int k = i >> 5, c4 = i & 31;
        *(float4*)&kvh[k * 128 + c4 * 4] =
            *(const float4*)&g_kv[(b * KCC + k) * CC + half * 128 + c4 * 4];
    }
    for (int i = tid; i < KCC * 16; i += 256) {
        int k = i >> 4, fx = i & 15;
        *(float4*)&qms[k * XLD + fx * 4] =
            *(const float4*)&g_qm[(size_t)(b * KCC + k) * NN + n0 + fx * 4];
    }
    if (tid < KCC) zsm[tid] = g_zf[b * KCC + tid];
    __syncthreads();

    float acc[8][4];
#pragma unroll
    for (int i = 0; i < 8; i++)
#pragma unroll
        for (int j = 0; j < 4; j++) acc[i][j] = 0.f;
    float qz[4] = {0.f, 0.f, 0.f, 0.f};

#pragma unroll 4
    for (int k = 0; k < KCC; k++) {
        float4 p = *(float4*)&qms[k * XLD + tx * 4];
        float zk = zsm[k];
        qz[0] = fmaf(zk, p.x, qz[0]);
        qz[1] = fmaf(zk, p.y, qz[1]);
        qz[2] = fmaf(zk, p.z, qz[2]);
        qz[3] = fmaf(zk, p.w, qz[3]);
        float4 a0 = *(float4*)&kvh[k * 128 + ty * 8];
        float4 a1 = *(float4*)&kvh[k * 128 + ty * 8 + 4];
        float av[8] = {a0.x, a0.y, a0.z, a0.w, a1.x, a1.y, a1.z, a1.w};
#pragma unroll
        for (int i = 0; i < 8; i++) {
            acc[i][0] = fmaf(av[i], p.x, acc[i][0]);
            acc[i][1] = fmaf(av[i], p.y, acc[i][1]);
            acc[i][2] = fmaf(av[i], p.z, acc[i][2]);
            acc[i][3] = fmaf(av[i], p.w, acc[i][3]);
        }
    }

    const float gam = gamma[0];
    float inv[4];
#pragma unroll
    for (int j = 0; j < 4; j++) inv[j] = gam / fmaxf(qz[j], 1e-6f);

#pragma unroll
    for (int i = 0; i < 8; i++) {
        int c = half * 128 + ty * 8 + i;
        size_t gidx = (size_t)(b * CC + c) * NN + n0 + tx * 4;
        float4 xv = *(const float4*)&x[gidx];
        float4 o;
        o.x = fmaf(acc[i][0], inv[0], xv.x);
        o.y = fmaf(acc[i][1], inv[1], xv.y);
        o.z = fmaf(acc[i][2], inv[2], xv.z);
        o.w = fmaf(acc[i][3], inv[3], xv.w);
        *(float4*)&out[gidx] = o;
    }
}

// ---------------------------------------------------------------------------
extern "C" void kernel_launch(void* const* d_in, const int* in_sizes, int n_in,
                              void* d_out, int out_size)
{
    const float* x     = (const float*)d_in[0];
    const float* Wq    = (const float*)d_in[1];
    const float* bq    = (const float*)d_in[2];
    const float* Wk    = (const float*)d_in[3];
    const float* bk    = (const float*)d_in[4];
    const float* Wv    = (const float*)d_in[5];
    const float* bv    = (const float*)d_in[6];
    const float* gamma = (const float*)d_in[7];
    float* out = (float*)d_out;

    size_t smem1 = (256 * 64 + 2 * 256 * XLD + KCC * XLD) * sizeof(float); // ~213 KB
    static int inited = 0;
    cudaFuncSetAttribute(pass1_kernel, cudaFuncAttributeMaxDynamicSharedMemorySize,
                         (int)smem1);
    (void)inited;

    zero_kernel<<<(BB * KCC * CC + 255) / 256, 256>>>();
    pass1_kernel<<<dim3(NBLK, BB), 256, smem1>>>(x, Wq, bq, Wk, bk);
    kv_kernel<<<dim3(8, BB), 256>>>(Wv, bv);
    pass2_kernel<<<dim3(NN / TP, 2, BB), 256>>>(x, gamma, out);
}

// round 5
// speedup vs baseline: 6.0324x; 2.1146x over previous
#include <cuda_runtime.h>
#include <cstdint>
#include <math.h>

#define BB   8
#define CC   256
#define KCC  32
#define NN   16384
#define TPX  128          // pass1 tile pixels
#define T1   4            // tiles per CTA
#define NB1  32           // CTAs per batch (32*4*128 = 16384)
#define TP   64           // pass2 tile pixels
#define XLD  68

#define LDW  260          // Ws row stride (floats), 260 % 32 == 4  -> conflict-free A frags
#define LDX  136          // xs row stride, 136 % 32 == 8           -> conflict-free B frags
#define LDK  132          // km row stride, 132 % 32 == 4           -> conflict-free A frags

// smem float offsets (pass1)
#define F_BIAS 0
#define F_WS   64
#define F_XS   (F_WS + 64 * LDW)          // 16704
#define F_KM   (F_XS + 256 * LDX)         // 51520
#define SMEM1_FLOATS (F_KM + 32 * LDK)    // 55744
#define SMEM1_BYTES  (SMEM1_FLOATS * 4)   // 222976

// Scratch (device globals)
__device__ __align__(16) float g_qm[(size_t)BB * KCC * NN]; // 16 MB fp32 [b][kc][n]
__device__ __align__(16) float g_S [BB * KCC * CC];
__device__ __align__(16) float g_z [BB * KCC];
__device__ __align__(16) float g_kv[BB * KCC * CC];
__device__ __align__(16) float g_zf[BB * KCC];

extern __shared__ float smf[];

__device__ __forceinline__ void cp_async16(uint32_t smem_dst, const void* gmem_src) {
    asm volatile("cp.async.cg.shared.global [%0], [%1], 16;\n" :: "r"(smem_dst), "l"(gmem_src));
}
__device__ __forceinline__ void cp_commit() {
    asm volatile("cp.async.commit_group;\n");
}
__device__ __forceinline__ void cp_wait_n(int n) {
    switch (n) {
        case 0: asm volatile("cp.async.wait_group 0;\n"); break;
        case 1: asm volatile("cp.async.wait_group 1;\n"); break;
        case 2: asm volatile("cp.async.wait_group 2;\n"); break;
        case 3: asm volatile("cp.async.wait_group 3;\n"); break;
        case 4: asm volatile("cp.async.wait_group 4;\n"); break;
        case 5: asm volatile("cp.async.wait_group 5;\n"); break;
        case 6: asm volatile("cp.async.wait_group 6;\n"); break;
        default: asm volatile("cp.async.wait_group 7;\n"); break;
    }
}
__device__ __forceinline__ uint32_t smem_u32(const void* p) {
    uint32_t a;
    asm("{ .reg .u64 t; cvta.to.shared.u64 t, %1; cvt.u32.u64 %0, t; }" : "=r"(a) : "l"(p));
    return a;
}
// m16n8k8 tf32 mma, fp32 operands (HW truncates mantissa)
__device__ __forceinline__ void mma_tf32(float d[4], const uint32_t a[4], const uint32_t b[2]) {
    asm volatile(
        "mma.sync.aligned.m16n8k8.row.col.f32.tf32.tf32.f32 "
        "{%0,%1,%2,%3}, {%4,%5,%6,%7}, {%8,%9}, {%0,%1,%2,%3};\n"
        : "+f"(d[0]), "+f"(d[1]), "+f"(d[2]), "+f"(d[3])
        : "r"(a[0]), "r"(a[1]), "r"(a[2]), "r"(a[3]), "r"(b[0]), "r"(b[1]));
}

// ---------------------------------------------------------------------------
__global__ void zero_kernel() {
    int i = blockIdx.x * 256 + threadIdx.x;
    if (i < BB * KCC * CC) g_S[i] = 0.f;
    if (i < BB * KCC) g_z[i] = 0.f;
}

// ---------------------------------------------------------------------------
// Pass 1 (mma.sync tf32): per 128-px tile
//   Stage B: D[qk,px] = Wqk[qk,c] . x[c,px]    (64x128x256)
//   epilogue: elu+1; q -> g_qm fp32; k -> km smem (+ z partials)
//   Stage C: S[kc,c] += km[kc,px] . x[c,px]^T  (32x256x128), S register-resident
// ---------------------------------------------------------------------------
__global__ __launch_bounds__(256, 1)
void pass1_kernel(const float* __restrict__ x,
                  const float* __restrict__ Wq, const float* __restrict__ bq,
                  const float* __restrict__ Wk, const float* __restrict__ bk)
{
    const int tid  = threadIdx.x;
    const int b    = blockIdx.y;
    const int blk  = blockIdx.x;
    const int w    = tid >> 5;
    const int lane = tid & 31;
    const int g    = lane >> 2;   // group id 0..7
    const int t    = lane & 3;    // thread-in-group 0..3

    const uint32_t sb = smem_u32(smf);
    const uint32_t* WsU = (const uint32_t*)(smf + F_WS);
    const uint32_t* xsU = (const uint32_t*)(smf + F_XS);
    const uint32_t* kmU = (const uint32_t*)(smf + F_KM);

    // bias + weights into smem (Ws[qk][c], row-major, LDW)
    if (tid < 64) smf[F_BIAS + tid] = (tid < KCC) ? bq[tid] : bk[tid - KCC];
    for (int i = tid; i < 64 * 256; i += 256) {
        int qk = i >> 8, c = i & 255;
        smf[F_WS + qk * LDW + c] = (qk < KCC) ? Wq[qk * CC + c] : Wk[(qk - KCC) * CC + c];
    }

    // S fragments: warp covers [32 kc] x [32 c at cbase]; persist across tiles
    float sc[2][4][4];
#pragma unroll
    for (int mi = 0; mi < 2; mi++)
#pragma unroll
        for (int nj = 0; nj < 4; nj++)
#pragma unroll
            for (int r = 0; r < 4; r++) sc[mi][nj][r] = 0.f;
    float zp[4] = {0.f, 0.f, 0.f, 0.f};

    const int qk0 = (w >> 2) * 32;       // 0 for warps 0-3 (q), 32 for 4-7 (k)
    const int px0 = (w & 3) * 32;
    const int cbase = w * 32;

    const float* xbase = x + (size_t)b * CC * NN;

    // issue tile-0 chunk copies (8 chunks of 32 c-rows)
    {
        const float* xb = xbase + (size_t)blk * T1 * TPX;
#pragma unroll
        for (int j = 0; j < 8; j++) {
            for (int u = tid; u < 1024; u += 256) {
                int row = u >> 5, seg = u & 31;
                int c = j * 32 + row;
                cp_async16(sb + (uint32_t)(F_XS + c * LDX + seg * 4) * 4,
                           xb + (size_t)c * NN + seg * 4);
            }
            cp_commit();
        }
    }
    __syncthreads();   // Ws/bias ready

    for (int tt = 0; tt < T1; tt++) {
        const int n0 = (blk * T1 + tt) * TPX;

        // ---- Stage B: chunk-pipelined k-loop ----
        float db[2][4][4];
#pragma unroll
        for (int mi = 0; mi < 2; mi++)
#pragma unroll
            for (int nj = 0; nj < 4; nj++)
#pragma unroll
                for (int r = 0; r < 4; r++) db[mi][nj][r] = 0.f;

#pragma unroll
        for (int j = 0; j < 8; j++) {
            cp_wait_n(7 - j);
            __syncthreads();
#pragma unroll
            for (int ss = 0; ss < 4; ss++) {
                const int c0 = j * 32 + ss * 8;
                uint32_t a[2][4];
#pragma unroll
                for (int mi = 0; mi < 2; mi++) {
                    int r0 = qk0 + 16 * mi + g;
                    a[mi][0] = WsU[r0 * LDW + c0 + t];
                    a[mi][1] = WsU[(r0 + 8) * LDW + c0 + t];
                    a[mi][2] = WsU[r0 * LDW + c0 + t + 4];
                    a[mi][3] = WsU[(r0 + 8) * LDW + c0 + t + 4];
                }
#pragma unroll
                for (int nj = 0; nj < 4; nj++) {
                    uint32_t bb[2];
                    bb[0] = xsU[(c0 + t) * LDX + px0 + 8 * nj + g];
                    bb[1] = xsU[(c0 + t + 4) * LDX + px0 + 8 * nj + g];
                    mma_tf32(db[0][nj], a[0], bb);
                    mma_tf32(db[1][nj], a[1], bb);
                }
            }
        }

        // ---- Epilogue: bias + elu+1 ----
        if (w < 4) {
            // q rows -> gmem fp32
#pragma unroll
            for (int mi = 0; mi < 2; mi++)
#pragma unroll
                for (int nj = 0; nj < 4; nj++)
#pragma unroll
                    for (int r = 0; r < 4; r++) {
                        int qk = 16 * mi + g + 8 * (r >> 1);
                        int px = px0 + 8 * nj + 2 * t + (r & 1);
                        float v = db[mi][nj][r] + smf[F_BIAS + qk];
                        v = (v > 0.f) ? (v + 1.f) : __expf(v);
                        g_qm[((size_t)b * KCC + qk) * NN + n0 + px] = v;
                    }
        } else {
            // k rows -> km smem + z partials
#pragma unroll
            for (int mi = 0; mi < 2; mi++)
#pragma unroll
                for (int nj = 0; nj < 4; nj++)
#pragma unroll
                    for (int r = 0; r < 4; r++) {
                        int kc = 16 * mi + g + 8 * (r >> 1);
                        int px = px0 + 8 * nj + 2 * t + (r & 1);
                        float v = db[mi][nj][r] + smf[F_BIAS + 32 + kc];
                        v = (v > 0.f) ? (v + 1.f) : __expf(v);
                        smf[F_KM + kc * LDK + px] = v;
                        zp[mi * 2 + (r >> 1)] += v;
                    }
        }
        __syncthreads();   // km visible to all

        // ---- Stage C: S[kc, cbase..+32] += km . xs^T over 128 px ----
#pragma unroll 4
        for (int s = 0; s < 16; s++) {
            const int p0 = s * 8;
            uint32_t a[2][4];
#pragma unroll
            for (int mi = 0; mi < 2; mi++) {
                int r0 = 16 * mi + g;
                a[mi][0] = kmU[r0 * LDK + p0 + t];
                a[mi][1] = kmU[(r0 + 8) * LDK + p0 + t];
                a[mi][2] = kmU[r0 * LDK + p0 + t + 4];
                a[mi][3] = kmU[(r0 + 8) * LDK + p0 + t + 4];
            }
#pragma unroll
            for (int nj = 0; nj < 4; nj++) {
                uint32_t bb[2];
                bb[0] = xsU[(cbase + 8 * nj + g) * LDX + p0 + t];
                bb[1] = xsU[(cbase + 8 * nj + g) * LDX + p0 + t + 4];
                mma_tf32(sc[0][nj], a[0], bb);
                mma_tf32(sc[1][nj], a[1], bb);
            }
        }
        __syncthreads();   // xs/km free to overwrite

        // issue next tile's chunk copies
        if (tt + 1 < T1) {
            const float* xb = xbase + (size_t)(blk * T1 + tt + 1) * TPX;
#pragma unroll
            for (int j = 0; j < 8; j++) {
                for (int u = tid; u < 1024; u += 256) {
                    int row = u >> 5, seg = u & 31;
                    int c = j * 32 + row;
                    cp_async16(sb + (uint32_t)(F_XS + c * LDX + seg * 4) * 4,
                               xb + (size_t)c * NN + seg * 4);
                }
                cp_commit();
            }
        }
    }

    // ---- Flush S ----
#pragma unroll
    for (int mi = 0; mi < 2; mi++)
#pragma unroll
        for (int nj = 0; nj < 4; nj++)
#pragma unroll
            for (int r = 0; r < 4; r++) {
                int kc = 16 * mi + g + 8 * (r >> 1);
                int c  = cbase + 8 * nj + 2 * t + (r & 1);
                atomicAdd(&g_S[(b * KCC + kc) * CC + c], sc[mi][nj][r]);
            }
    // ---- Flush z (warps 4-7 hold partials) ----
    if (w >= 4) {
#pragma unroll
        for (int i = 0; i < 4; i++) {
            float v = zp[i];
            v += __shfl_xor_sync(0xffffffffu, v, 1);
            v += __shfl_xor_sync(0xffffffffu, v, 2);
            if (t == 0) {
                int kc = 16 * (i >> 1) + 8 * (i & 1) + g;
                atomicAdd(&g_z[b * KCC + kc], v);
            }
        }
    }
}

// ---------------------------------------------------------------------------
// kv = S @ Wv^T + z * bv^T    grid (8 vslices, 8 batches)
// ---------------------------------------------------------------------------
__global__ __launch_bounds__(256)
void kv_kernel(const float* __restrict__ Wv, const float* __restrict__ bv)
{
    __shared__ float Ssm[KCC * CC];
    __shared__ float Wsm[32 * CC];
    __shared__ float zsm[KCC];

    const int tid = threadIdx.x;
    const int b   = blockIdx.y;
    const int v0  = blockIdx.x * 32;

    for (int i = tid; i < KCC * CC / 4; i += 256)
        *(float4*)&Ssm[i * 4] = *(const float4*)&g_S[b * KCC * CC + i * 4];
    for (int i = tid; i < 32 * CC / 4; i += 256)
        *(float4*)&Wsm[i * 4] = *(const float4*)&Wv[v0 * CC + i * 4];
    if (tid < KCC) {
        float z = g_z[b * KCC + tid];
        zsm[tid] = z;
        if (blockIdx.x == 0) g_zf[b * KCC + tid] = z;
    }
    __syncthreads();

    const int kc = tid >> 3, j0 = tid & 7;
#pragma unroll
    for (int j = 0; j < 4; j++) {
        int vl = j0 + 8 * j;
        float acc = zsm[kc] * bv[v0 + vl];
        const float* wr = Wsm + vl * CC;
        const float* sr = Ssm + kc * CC;
#pragma unroll 8
        for (int c4 = 0; c4 < 64; c4++) {
            float4 wv = *(const float4*)&wr[c4 * 4];
            float4 s  = *(const float4*)&sr[c4 * 4];
            acc = fmaf(wv.x, s.x, acc);
            acc = fmaf(wv.y, s.y, acc);
            acc = fmaf(wv.z, s.z, acc);
            acc = fmaf(wv.w, s.w, acc);
        }
        g_kv[(b * KCC + kc) * CC + v0 + vl] = acc;
    }
}

// ---------------------------------------------------------------------------
// Pass 2: out = gamma * (kv^T @ qm) / max(qm . z, 1e-6) + x
// ---------------------------------------------------------------------------
__global__ __launch_bounds__(256)
void pass2_kernel(const float* __restrict__ x,
                  const float* __restrict__ gamma,
                  float* __restrict__ out)
{
    __shared__ float kvh[KCC * 128];
    __shared__ float qms[KCC * XLD];
    __shared__ float zsm[KCC];

    const int tid  = threadIdx.x;
    const int b    = blockIdx.z;
    const int half = blockIdx.y;
    const int n0   = blockIdx.x * TP;
    const int ty   = tid >> 4;
    const int tx   = tid & 15;

    for (int i = tid; i < KCC * 32; i += 256) {
        int k = i >> 5, c4 = i & 31;
        *(float4*)&kvh[k * 128 + c4 * 4] =
            *(const float4*)&g_kv[(b * KCC + k) * CC + half * 128 + c4 * 4];
    }
    for (int i = tid; i < KCC * 16; i += 256) {
        int k = i >> 4, fx = i & 15;
        *(float4*)&qms[k * XLD + fx * 4] =
            *(const float4*)&g_qm[((size_t)b * KCC + k) * NN + n0 + fx * 4];
    }
    if (tid < KCC) zsm[tid] = g_zf[b * KCC + tid];
    __syncthreads();

    float acc[8][4];
#pragma unroll
    for (int i = 0; i < 8; i++)
#pragma unroll
        for (int j = 0; j < 4; j++) acc[i][j] = 0.f;
    float qz[4] = {0.f, 0.f, 0.f, 0.f};

#pragma unroll 4
    for (int k = 0; k < KCC; k++) {
        float4 p = *(float4*)&qms[k * XLD + tx * 4];
        float zk = zsm[k];
        qz[0] = fmaf(zk, p.x, qz[0]);
        qz[1] = fmaf(zk, p.y, qz[1]);
        qz[2] = fmaf(zk, p.z, qz[2]);
        qz[3] = fmaf(zk, p.w, qz[3]);
        float4 a0 = *(float4*)&kvh[k * 128 + ty * 8];
        float4 a1 = *(float4*)&kvh[k * 128 + ty * 8 + 4];
        float av[8] = {a0.x, a0.y, a0.z, a0.w, a1.x, a1.y, a1.z, a1.w};
#pragma unroll
        for (int i = 0; i < 8; i++) {
            acc[i][0] = fmaf(av[i], p.x, acc[i][0]);
            acc[i][1] = fmaf(av[i], p.y, acc[i][1]);
            acc[i][2] = fmaf(av[i], p.z, acc[i][2]);
            acc[i][3] = fmaf(av[i], p.w, acc[i][3]);
        }
    }

    const float gam = gamma[0];
    float inv[4];
#pragma unroll
    for (int j = 0; j < 4; j++) inv[j] = gam / fmaxf(qz[j], 1e-6f);

#pragma unroll
    for (int i = 0; i < 8; i++) {
        int c = half * 128 + ty * 8 + i;
        size_t gidx = ((size_t)b * CC + c) * NN + n0 + tx * 4;
        float4 xv = *(const float4*)&x[gidx];
        float4 o;
        o.x = fmaf(acc[i][0], inv[0], xv.x);
        o.y = fmaf(acc[i][1], inv[1], xv.y);
        o.z = fmaf(acc[i][2], inv[2], xv.z);
        o.w = fmaf(acc[i][3], inv[3], xv.w);
        *(float4*)&out[gidx] = o;
    }
}

// ---------------------------------------------------------------------------
extern "C" void kernel_launch(void* const* d_in, const int* in_sizes, int n_in,
                              void* d_out, int out_size)
{
    const float* x     = (const float*)d_in[0];
    const float* Wq    = (const float*)d_in[1];
    const float* bq    = (const float*)d_in[2];
    const float* Wk    = (const float*)d_in[3];
    const float* bk    = (const float*)d_in[4];
    const float* Wv    = (const float*)d_in[5];
    const float* bv    = (const float*)d_in[6];
    const float* gamma = (const float*)d_in[7];
    float* out = (float*)d_out;

    cudaFuncSetAttribute(pass1_kernel, cudaFuncAttributeMaxDynamicSharedMemorySize,
                         SMEM1_BYTES);

    zero_kernel<<<(BB * KCC * CC + 255) / 256, 256>>>();
    pass1_kernel<<<dim3(NB1, BB), 256, SMEM1_BYTES>>>(x, Wq, bq, Wk, bk);
    kv_kernel<<<dim3(8, BB), 256>>>(Wv, bv);
    pass2_kernel<<<dim3(NN / TP, 2, BB), 256>>>(x, gamma, out);
}